// round 3
// baseline (speedup 1.0000x reference)
#include <cuda_runtime.h>
#include <cstdint>

#define NB      256   // batch
#define DIN     256   // input channels
#define DH      512   // hidden channels
#define WDIM    8
#define PIX     64    // 8x8
#define CB      32    // hidden channels per block
#define ROWS    128   // 4 gates * CB
#define CIC     8     // input-channel chunk staged in smem
#define THREADS 256

typedef unsigned long long ull;

// ---- packed f32x2 helpers (Blackwell sm_103a) ----
__device__ __forceinline__ ull pk(float lo, float hi) {
    ull r; asm("mov.b64 %0, {%1, %2};" : "=l"(r) : "f"(lo), "f"(hi)); return r;
}
__device__ __forceinline__ void fma2(ull& d, ull a, ull b) {
    asm("fma.rn.f32x2 %0, %1, %2, %0;" : "+l"(d) : "l"(a), "l"(b));
}
__device__ __forceinline__ float2 upk(ull v) {
    float2 r; asm("mov.b64 {%0, %1}, %2;" : "=f"(r.x), "=f"(r.y) : "l"(v)); return r;
}

// One 3x3 reflect-padded conv accumulated into acc[4 rows][4 pixel-pairs].
// Rows r0..r0+3 index into the 128-row (4 gates x 32 ch) output tile.
__device__ __forceinline__ void conv_pass(
    const float* __restrict__ src,          // [CIN, 8, 8] for this image
    const float* w0, const float* w1, const float* w2, const float* w3,
    int CIN, int c_base, int t, int pg, int r0,
    ull acc[4][4], float* s_in, float* s_w)
{
    const float* wptr[4] = {w0, w1, w2, w3};
    for (int cib = 0; cib < CIN; cib += CIC) {
        __syncthreads();
        // Stage input tile with reflect padding: CIC x 10 x 10
        for (int i = t; i < CIC * 100; i += THREADS) {
            int ci = i / 100; int p = i - ci * 100;
            int yy = p / 10;  int xx = p - yy * 10;
            int ry = (yy == 0) ? 1 : ((yy == 9) ? 6 : yy - 1);
            int rx = (xx == 0) ? 1 : ((xx == 9) ? 6 : xx - 1);
            s_in[i] = src[(size_t)(cib + ci) * PIX + ry * WDIM + rx];
        }
        // Stage weights: ROWS x CIC x 9 floats (float2 vectorized, aligned)
        for (int i = t; i < ROWS * (CIC * 9 / 2); i += THREADS) {
            int r = i / 36; int rem = i - r * 36;
            int g = r >> 5; int c = c_base + (r & 31);
            const float2* wsrc = reinterpret_cast<const float2*>(
                wptr[g] + ((size_t)c * CIN + cib) * 9);
            reinterpret_cast<float2*>(s_w)[i] = wsrc[rem];
        }
        __syncthreads();

        for (int ci = 0; ci < CIC; ci++) {
            // Load the 3 padded input rows this thread's output row needs,
            // as even pairs E[k]=(v[2k],v[2k+1]) and odd pairs O[k]=(v[2k+1],v[2k+2]).
            ull E[3][5], O[3][4];
            #pragma unroll
            for (int dy = 0; dy < 3; dy++) {
                const float2* rp = reinterpret_cast<const float2*>(
                    &s_in[ci * 100 + (pg + dy) * 10]);
                float2 e0 = rp[0], e1 = rp[1], e2 = rp[2], e3 = rp[3], e4 = rp[4];
                E[dy][0] = pk(e0.x, e0.y);
                E[dy][1] = pk(e1.x, e1.y);
                E[dy][2] = pk(e2.x, e2.y);
                E[dy][3] = pk(e3.x, e3.y);
                E[dy][4] = pk(e4.x, e4.y);
                O[dy][0] = pk(e0.y, e1.x);
                O[dy][1] = pk(e1.y, e2.x);
                O[dy][2] = pk(e2.y, e3.x);
                O[dy][3] = pk(e3.y, e4.x);
            }
            #pragma unroll
            for (int r = 0; r < 4; r++) {
                const float* wr = &s_w[(r0 + r) * (CIC * 9) + ci * 9];
                #pragma unroll
                for (int dy = 0; dy < 3; dy++) {
                    ull wA = pk(wr[dy * 3 + 0], wr[dy * 3 + 0]);
                    ull wB = pk(wr[dy * 3 + 1], wr[dy * 3 + 1]);
                    ull wC = pk(wr[dy * 3 + 2], wr[dy * 3 + 2]);
                    // out[x pair p] covers px (2p, 2p+1):
                    //  dx=0 -> E[p], dx=1 -> O[p], dx=2 -> E[p+1]
                    #pragma unroll
                    for (int p = 0; p < 4; p++) {
                        fma2(acc[r][p], wA, E[dy][p]);
                        fma2(acc[r][p], wB, O[dy][p]);
                        fma2(acc[r][p], wC, E[dy][p + 1]);
                    }
                }
            }
        }
    }
}

__global__ void __launch_bounds__(THREADS, 2) convlstm_kernel(
    const float* __restrict__ x,   const float* __restrict__ hs,
    const float* __restrict__ wii, const float* __restrict__ wif_,
    const float* __restrict__ wig, const float* __restrict__ wio,
    const float* __restrict__ whi, const float* __restrict__ whf,
    const float* __restrict__ whg, const float* __restrict__ who,
    const float* __restrict__ bi,  const float* __restrict__ bf,
    const float* __restrict__ bg,  const float* __restrict__ bo,
    const float* __restrict__ wci, const float* __restrict__ wcf,
    const float* __restrict__ wco,
    float* __restrict__ out)
{
    // Union: during conv loop [s_in (800) | s_w (9216)]; afterwards s_pre (8192).
    __shared__ float smem[10048];
    float* s_in  = smem;
    float* s_w   = smem + CIC * 100;
    float* s_pre = smem;

    const int t  = threadIdx.x;
    const int pg = t & 7;          // output row y (0..7)
    const int r0 = (t >> 3) * 4;   // first of 4 gate-rows this thread owns
    const int n  = blockIdx.y;
    const int c_base = blockIdx.x * CB;

    ull acc[4][4] = {};  // 4 rows x 4 pixel-pairs, packed fp32 pairs (zero = 0.0f,0.0f)

    // pre = conv(x_pad, w_x) + conv(h0_pad, w_h)
    conv_pass(x  + (size_t)n * DIN * PIX,       wii, wif_, wig, wio,
              DIN, c_base, t, pg, r0, acc, s_in, s_w);
    conv_pass(hs + (size_t)(n * 2) * DH * PIX,  whi, whf, whg, who,
              DH,  c_base, t, pg, r0, acc, s_in, s_w);

    __syncthreads();   // all reads of s_in/s_w done before aliasing as s_pre
    #pragma unroll
    for (int r = 0; r < 4; r++) {
        #pragma unroll
        for (int p = 0; p < 4; p++) {
            float2 v = upk(acc[r][p]);
            s_pre[(r0 + r) * PIX + pg * 8 + 2 * p]     = v.x;
            s_pre[(r0 + r) * PIX + pg * 8 + 2 * p + 1] = v.y;
        }
    }
    __syncthreads();

    // Gate math + outputs. Rows: gate g channel cl lives at row g*32+cl.
    const float* c0p = hs + ((size_t)(n * 2) + 1) * DH * PIX;
    const size_t base2 = (size_t)NB * DH * PIX;   // start of hidden_state_out
    for (int e = t; e < CB * PIX; e += THREADS) {
        int cl = e >> 6; int px = e & 63;
        int c = c_base + cl;
        float pi  = s_pre[(cl)      * PIX + px] + bi[c];
        float pf  = s_pre[(32 + cl) * PIX + px] + bf[c];
        float pgv = s_pre[(64 + cl) * PIX + px] + bg[c];
        float po  = s_pre[(96 + cl) * PIX + px] + bo[c];

        float c0 = c0p[(size_t)c * PIX + px];
        float vi = wci[c * PIX + px];
        float vf = wcf[c * PIX + px];
        float vo = wco[c * PIX + px];

        float ig = 1.f / (1.f + expf(-(pi + c0 * vi)));
        float fg = 1.f / (1.f + expf(-(pf + c0 * vf)));
        float gg = tanhf(pgv);
        float ct = fg * c0 + ig * gg;
        float og = 1.f / (1.f + expf(-(po + ct * vo)));
        float ht = og * tanhf(ct);

        out[((size_t)n * DH + c) * PIX + px] = og;                              // o
        out[base2 + (((size_t)n * 2) * DH + c) * PIX + px]     = ht;            // h_t
        out[base2 + (((size_t)n * 2 + 1) * DH + c) * PIX + px] = ct;            // c_t
    }
}

extern "C" void kernel_launch(void* const* d_in, const int* in_sizes, int n_in,
                              void* d_out, int out_size) {
    (void)in_sizes; (void)n_in; (void)out_size;
    const float* x    = (const float*)d_in[0];
    const float* hs   = (const float*)d_in[1];
    const float* wii  = (const float*)d_in[2];
    const float* wif_ = (const float*)d_in[3];
    const float* wig  = (const float*)d_in[4];
    const float* wio  = (const float*)d_in[5];
    const float* whi  = (const float*)d_in[6];
    const float* whf  = (const float*)d_in[7];
    const float* whg  = (const float*)d_in[8];
    const float* who  = (const float*)d_in[9];
    const float* bi   = (const float*)d_in[10];
    const float* bf   = (const float*)d_in[11];
    const float* bg   = (const float*)d_in[12];
    const float* bo   = (const float*)d_in[13];
    const float* wci  = (const float*)d_in[14];
    const float* wcf  = (const float*)d_in[15];
    const float* wco  = (const float*)d_in[16];

    dim3 grid(DH / CB, NB);   // 16 channel-chunks x 256 images
    convlstm_kernel<<<grid, THREADS>>>(
        x, hs, wii, wif_, wig, wio, whi, whf, whg, who,
        bi, bf, bg, bo, wci, wcf, wco, (float*)d_out);
}

// round 5
// speedup vs baseline: 4.7437x; 4.7437x over previous
#include <cuda_runtime.h>
#include <cuda_bf16.h>
#include <cstdint>

#define DIN   256
#define DH    512
#define NB    256
#define KTOT  6912
#define KX    2304
#define MTOT  2048
#define NTOT  16384
#define BK    64
#define NITER (KTOT/BK)      // 108
#define GT    256
#define BUFSZ 98304          // Ah16K + Al16K + Bh32K + Bl32K
#define SMEM_BYTES (2*BUFSZ) // 192KB

__device__ __align__(16) __nv_bfloat16 g_Ah[(size_t)MTOT*KTOT];
__device__ __align__(16) __nv_bfloat16 g_Al[(size_t)MTOT*KTOT];
__device__ __align__(16) __nv_bfloat16 g_Bh[(size_t)NTOT*KTOT];
__device__ __align__(16) __nv_bfloat16 g_Bl[(size_t)NTOT*KTOT];

__device__ __forceinline__ uint32_t smem_u32(const void* p) {
    uint32_t a;
    asm("{ .reg .u64 t; cvta.to.shared.u64 t, %1; cvt.u32.u64 %0, t; }" : "=r"(a) : "l"(p));
    return a;
}
__device__ __forceinline__ void cp16(uint32_t dst, const void* src) {
    asm volatile("cp.async.cg.shared.global [%0], [%1], 16;" :: "r"(dst), "l"(src));
}
__device__ __forceinline__ void cp_commit() { asm volatile("cp.async.commit_group;"); }
template<int N> __device__ __forceinline__ void cp_wait() {
    asm volatile("cp.async.wait_group %0;" :: "n"(N));
}
__device__ __forceinline__ void ldsm4(uint32_t* r, uint32_t a) {
    asm volatile("ldmatrix.sync.aligned.m8n8.x4.shared.b16 {%0,%1,%2,%3}, [%4];"
                 : "=r"(r[0]), "=r"(r[1]), "=r"(r[2]), "=r"(r[3]) : "r"(a));
}
__device__ __forceinline__ void mma_bf16(float* d, const uint32_t* a, const uint32_t* b) {
    asm volatile(
        "mma.sync.aligned.m16n8k16.row.col.f32.bf16.bf16.f32 "
        "{%0,%1,%2,%3}, {%4,%5,%6,%7}, {%8,%9}, {%0,%1,%2,%3};"
        : "+f"(d[0]), "+f"(d[1]), "+f"(d[2]), "+f"(d[3])
        : "r"(a[0]), "r"(a[1]), "r"(a[2]), "r"(a[3]), "r"(b[0]), "r"(b[1]));
}

// ---------------- prep: weights -> A (row = cb*128 + gate*32 + ch), hi/lo bf16
__global__ void prep_a(const float* __restrict__ wii, const float* __restrict__ wif_,
                       const float* __restrict__ wig, const float* __restrict__ wio,
                       const float* __restrict__ whi, const float* __restrict__ whf,
                       const float* __restrict__ whg, const float* __restrict__ who) {
    size_t idx = (size_t)blockIdx.x * blockDim.x + threadIdx.x;
    if (idx >= (size_t)MTOT * KTOT) return;
    int m = (int)(idx / KTOT);
    int k = (int)(idx - (size_t)m * KTOT);
    int cb = m >> 7, g = (m >> 5) & 3, cl = m & 31;
    int c = cb * 32 + cl;
    const float* wx = (g == 0) ? wii : (g == 1) ? wif_ : (g == 2) ? wig : wio;
    const float* wh = (g == 0) ? whi : (g == 1) ? whf : (g == 2) ? whg : who;
    float v = (k < KX) ? wx[(size_t)c * KX + k] : wh[(size_t)c * (KTOT - KX) + (k - KX)];
    __nv_bfloat16 h = __float2bfloat16(v);
    g_Ah[idx] = h;
    g_Al[idx] = __float2bfloat16(v - __bfloat162float(h));
}

// ---------------- prep: im2col with reflect padding -> B[ncol][k], hi/lo bf16
__global__ void prep_b(const float* __restrict__ x, const float* __restrict__ hs) {
    __shared__ __nv_bfloat16 s_h[KTOT];
    __shared__ __nv_bfloat16 s_l[KTOT];
    int ncol = blockIdx.x;
    int n = ncol >> 6, py = (ncol >> 3) & 7, px = ncol & 7;
    int ry[3], rx[3];
#pragma unroll
    for (int d = 0; d < 3; d++) {
        int p = py + d - 1; ry[d] = (p < 0) ? 1 : (p > 7 ? 6 : p);
        int q = px + d - 1; rx[d] = (q < 0) ? 1 : (q > 7 ? 6 : q);
    }
    for (int cin = threadIdx.x; cin < 768; cin += blockDim.x) {
        const float* src = (cin < DIN)
            ? x  + ((size_t)n * DIN + cin) * 64
            : hs + (((size_t)n * 2) * DH + (cin - DIN)) * 64;
        int kb = cin * 9;
#pragma unroll
        for (int ky = 0; ky < 3; ky++)
#pragma unroll
            for (int kx = 0; kx < 3; kx++) {
                float v = src[ry[ky] * 8 + rx[kx]];
                __nv_bfloat16 h = __float2bfloat16(v);
                s_h[kb + ky * 3 + kx] = h;
                s_l[kb + ky * 3 + kx] = __float2bfloat16(v - __bfloat162float(h));
            }
    }
    __syncthreads();
    const uint4* sh = (const uint4*)s_h;
    const uint4* sl = (const uint4*)s_l;
    uint4* dh = (uint4*)(g_Bh + (size_t)ncol * KTOT);
    uint4* dl = (uint4*)(g_Bl + (size_t)ncol * KTOT);
    for (int i = threadIdx.x; i < KTOT * 2 / 16; i += blockDim.x) {
        dh[i] = sh[i]; dl[i] = sl[i];
    }
}

// ---------------- GEMM (mma.sync bf16 3-pass) + fused LSTM epilogue
__global__ void __launch_bounds__(GT, 1) gemm_lstm(
    const float* __restrict__ hs,
    const float* __restrict__ bi, const float* __restrict__ bf_,
    const float* __restrict__ bg, const float* __restrict__ bo,
    const float* __restrict__ wci, const float* __restrict__ wcf,
    const float* __restrict__ wco, float* __restrict__ out)
{
    extern __shared__ char smem[];
    const uint32_t sb = smem_u32(smem);
    const int tid = threadIdx.x;
    const int wid = tid >> 5, lane = tid & 31;
    const int wm = wid & 1, wn = wid >> 1;   // 2 x 4 warp grid
    const int mt = blockIdx.x, nt = blockIdx.y;
    const int m0 = mt * 128, n0 = nt * 256;

    float acc[4][8][4];
#pragma unroll
    for (int i = 0; i < 4; i++)
#pragma unroll
        for (int j = 0; j < 8; j++)
#pragma unroll
            for (int v = 0; v < 4; v++) acc[i][j][v] = 0.f;

    // cp.async stage loader: 6144 x 16B, swizzled (c ^= r&7) 128B rows
    auto issue_stage = [&](int kc, int buf) {
        const uint32_t st = sb + buf * BUFSZ;
        const size_t kof = (size_t)kc * BK;
#pragma unroll
        for (int i = tid; i < 6144; i += GT) {
            uint32_t dst; const __nv_bfloat16* src;
            if (i < 2048) {          // A hi/lo: 128 rows x 8 chunks
                int arr = i >> 10, j = i & 1023, r = j >> 3, c = j & 7;
                src = (arr ? g_Al : g_Ah) + (size_t)(m0 + r) * KTOT + kof + c * 8;
                dst = st + arr * 16384 + r * 128 + ((c ^ (r & 7)) << 4);
            } else {                 // B hi/lo: 256 rows x 8 chunks
                int j = i - 2048; int arr = j >> 11; j &= 2047;
                int r = j >> 3, c = j & 7;
                src = (arr ? g_Bl : g_Bh) + (size_t)(n0 + r) * KTOT + kof + c * 8;
                dst = st + 32768 + arr * 32768 + r * 128 + ((c ^ (r & 7)) << 4);
            }
            cp16(dst, src);
        }
        cp_commit();
    };

    issue_stage(0, 0);

    for (int kc = 0; kc < NITER; kc++) {
        const int buf = kc & 1;
        if (kc + 1 < NITER) { issue_stage(kc + 1, buf ^ 1); cp_wait<1>(); }
        else                { cp_wait<0>(); }
        __syncthreads();

        const uint32_t st = sb + buf * BUFSZ;
#pragma unroll
        for (int kk = 0; kk < 4; kk++) {          // four k16 steps
            uint32_t a_h[4][4], a_l[4][4];
#pragma unroll
            for (int mi = 0; mi < 4; mi++) {
                int r = wm * 64 + mi * 16 + (lane & 15);
                int c = kk * 2 + (lane >> 4);
                uint32_t off = r * 128 + ((c ^ (r & 7)) << 4);
                ldsm4(a_h[mi], st + off);
                ldsm4(a_l[mi], st + 16384 + off);
            }
            uint32_t b_h[4][4], b_l[4][4];
#pragma unroll
            for (int nj = 0; nj < 4; nj++) {
                int r = wn * 64 + nj * 16 + (lane & 7) + ((lane >> 4) << 3);
                int c = kk * 2 + ((lane >> 3) & 1);
                uint32_t off = r * 128 + ((c ^ (r & 7)) << 4);
                ldsm4(b_h[nj], st + 32768 + off);
                ldsm4(b_l[nj], st + 65536 + off);
            }
#pragma unroll
            for (int mi = 0; mi < 4; mi++)
#pragma unroll
                for (int nj = 0; nj < 4; nj++) {
#pragma unroll
                    for (int s = 0; s < 2; s++) {
                        float* d = acc[mi][nj * 2 + s];
                        mma_bf16(d, a_h[mi], &b_h[nj][s * 2]);   // Ah*Bh
                        mma_bf16(d, a_h[mi], &b_l[nj][s * 2]);   // Ah*Bl
                        mma_bf16(d, a_l[mi], &b_h[nj][s * 2]);   // Al*Bh
                    }
                }
        }
        __syncthreads();
    }

    // ---- epilogue: acc -> smem pre[128][260], then fused LSTM ----
    float* pre = (float*)smem;
    const int lr = lane >> 2, lc = (lane & 3) * 2;
#pragma unroll
    for (int mi = 0; mi < 4; mi++)
#pragma unroll
        for (int ni = 0; ni < 8; ni++) {
            int r = wm * 64 + mi * 16 + lr;
            int c = wn * 64 + ni * 8 + lc;
            pre[r * 260 + c]           = acc[mi][ni][0];
            pre[r * 260 + c + 1]       = acc[mi][ni][1];
            pre[(r + 8) * 260 + c]     = acc[mi][ni][2];
            pre[(r + 8) * 260 + c + 1] = acc[mi][ni][3];
        }
    __syncthreads();

    const size_t base2 = (size_t)NB * DH * 64;
    for (int e = tid; e < 4 * 2048; e += GT) {
        int img = e >> 11, cl = (e >> 6) & 31, pix = e & 63;
        int col = img * 64 + pix;
        int n = nt * 4 + img;
        int c = mt * 32 + cl;
        const float* c0p = hs + ((size_t)(n * 2) + 1) * DH * 64;

        float pi = pre[(cl)      * 260 + col] + bi[c];
        float pf = pre[(32 + cl) * 260 + col] + bf_[c];
        float pg = pre[(64 + cl) * 260 + col] + bg[c];
        float po = pre[(96 + cl) * 260 + col] + bo[c];
        float c0 = c0p[(size_t)c * 64 + pix];
        float ig = 1.f / (1.f + expf(-(pi + c0 * wci[c * 64 + pix])));
        float fg = 1.f / (1.f + expf(-(pf + c0 * wcf[c * 64 + pix])));
        float gg = tanhf(pg);
        float ct = fg * c0 + ig * gg;
        float og = 1.f / (1.f + expf(-(po + ct * wco[c * 64 + pix])));
        float ht = og * tanhf(ct);
        out[((size_t)n * DH + c) * 64 + pix] = og;
        out[base2 + (((size_t)n * 2) * DH + c) * 64 + pix] = ht;
        out[base2 + (((size_t)n * 2 + 1) * DH + c) * 64 + pix] = ct;
    }
}

extern "C" void kernel_launch(void* const* d_in, const int* in_sizes, int n_in,
                              void* d_out, int out_size) {
    (void)in_sizes; (void)n_in; (void)out_size;
    const float* x  = (const float*)d_in[0];
    const float* hs = (const float*)d_in[1];

    static int configured = 0;
    if (!configured) {
        cudaFuncSetAttribute(gemm_lstm, cudaFuncAttributeMaxDynamicSharedMemorySize,
                             SMEM_BYTES);
        configured = 1;
    }

    prep_a<<<(int)(((size_t)MTOT * KTOT + 255) / 256), 256>>>(
        (const float*)d_in[2], (const float*)d_in[3], (const float*)d_in[4],
        (const float*)d_in[5], (const float*)d_in[6], (const float*)d_in[7],
        (const float*)d_in[8], (const float*)d_in[9]);
    prep_b<<<NTOT, 256>>>(x, hs);

    dim3 grid(MTOT / 128, NTOT / 256);   // 16 x 64
    gemm_lstm<<<grid, GT, SMEM_BYTES>>>(
        hs,
        (const float*)d_in[10], (const float*)d_in[11],
        (const float*)d_in[12], (const float*)d_in[13],
        (const float*)d_in[14], (const float*)d_in[15], (const float*)d_in[16],
        (float*)d_out);
}

// round 6
// speedup vs baseline: 10.2467x; 2.1601x over previous
#include <cuda_runtime.h>
#include <cuda_fp16.h>
#include <cstdint>

#define DIN   256
#define DH    512
#define NB    256
#define KTOT  6912
#define KX    2304
#define MTOT  2048
#define NTOT  16384
#define BK    64
#define NITER (KTOT/BK)      // 108
#define GT    256
#define STG   49152          // A 16KB + B 32KB
#define NSTG  4
#define SMEM_BYTES (NSTG*STG) // 192KB

__device__ __align__(16) __half g_A[(size_t)MTOT*KTOT];
__device__ __align__(16) __half g_B[(size_t)NTOT*KTOT];

__device__ __forceinline__ uint32_t smem_u32(const void* p) {
    uint32_t a;
    asm("{ .reg .u64 t; cvta.to.shared.u64 t, %1; cvt.u32.u64 %0, t; }" : "=r"(a) : "l"(p));
    return a;
}
__device__ __forceinline__ void cp16(uint32_t dst, const void* src) {
    asm volatile("cp.async.cg.shared.global [%0], [%1], 16;" :: "r"(dst), "l"(src));
}
__device__ __forceinline__ void cp_commit() { asm volatile("cp.async.commit_group;"); }
template<int N> __device__ __forceinline__ void cp_wait() {
    asm volatile("cp.async.wait_group %0;" :: "n"(N));
}
__device__ __forceinline__ void ldsm4(uint32_t* r, uint32_t a) {
    asm volatile("ldmatrix.sync.aligned.m8n8.x4.shared.b16 {%0,%1,%2,%3}, [%4];"
                 : "=r"(r[0]), "=r"(r[1]), "=r"(r[2]), "=r"(r[3]) : "r"(a));
}
__device__ __forceinline__ void mma_f16(float* d, const uint32_t* a, const uint32_t* b) {
    asm volatile(
        "mma.sync.aligned.m16n8k16.row.col.f32.f16.f16.f32 "
        "{%0,%1,%2,%3}, {%4,%5,%6,%7}, {%8,%9}, {%0,%1,%2,%3};"
        : "+f"(d[0]), "+f"(d[1]), "+f"(d[2]), "+f"(d[3])
        : "r"(a[0]), "r"(a[1]), "r"(a[2]), "r"(a[3]), "r"(b[0]), "r"(b[1]));
}

// ---- prep: weights -> A fp16 (row = cb*128 + gate*32 + ch) ----
__global__ void prep_a(const float* __restrict__ wii, const float* __restrict__ wif_,
                       const float* __restrict__ wig, const float* __restrict__ wio,
                       const float* __restrict__ whi, const float* __restrict__ whf,
                       const float* __restrict__ whg, const float* __restrict__ who) {
    size_t idx = (size_t)blockIdx.x * blockDim.x + threadIdx.x;
    if (idx >= (size_t)MTOT * KTOT) return;
    int m = (int)(idx / KTOT);
    int k = (int)(idx - (size_t)m * KTOT);
    int cb = m >> 7, g = (m >> 5) & 3, cl = m & 31;
    int c = cb * 32 + cl;
    const float* wx = (g == 0) ? wii : (g == 1) ? wif_ : (g == 2) ? wig : wio;
    const float* wh = (g == 0) ? whi : (g == 1) ? whf : (g == 2) ? whg : who;
    float v = (k < KX) ? wx[(size_t)c * KX + k] : wh[(size_t)c * (KTOT - KX) + (k - KX)];
    g_A[idx] = __float2half(v);
}

// ---- prep: im2col with reflect padding -> B fp16 ----
__global__ void prep_b(const float* __restrict__ x, const float* __restrict__ hs) {
    __shared__ __half s_h[KTOT];
    int ncol = blockIdx.x;
    int n = ncol >> 6, py = (ncol >> 3) & 7, px = ncol & 7;
    int ry[3], rx[3];
#pragma unroll
    for (int d = 0; d < 3; d++) {
        int p = py + d - 1; ry[d] = (p < 0) ? 1 : (p > 7 ? 6 : p);
        int q = px + d - 1; rx[d] = (q < 0) ? 1 : (q > 7 ? 6 : q);
    }
    for (int cin = threadIdx.x; cin < 768; cin += blockDim.x) {
        const float* src = (cin < DIN)
            ? x  + ((size_t)n * DIN + cin) * 64
            : hs + (((size_t)n * 2) * DH + (cin - DIN)) * 64;
        int kb = cin * 9;
#pragma unroll
        for (int ky = 0; ky < 3; ky++)
#pragma unroll
            for (int kx = 0; kx < 3; kx++)
                s_h[kb + ky * 3 + kx] = __float2half(src[ry[ky] * 8 + rx[kx]]);
    }
    __syncthreads();
    const uint4* sh = (const uint4*)s_h;
    uint4* dh = (uint4*)(g_B + (size_t)ncol * KTOT);
    for (int i = threadIdx.x; i < KTOT * 2 / 16; i += blockDim.x) dh[i] = sh[i];
}

// ---- GEMM (single-pass fp16 mma.sync) + fused LSTM epilogue ----
__global__ void __launch_bounds__(GT, 1) gemm_lstm(
    const float* __restrict__ hs,
    const float* __restrict__ bi, const float* __restrict__ bf_,
    const float* __restrict__ bg, const float* __restrict__ bo,
    const float* __restrict__ wci, const float* __restrict__ wcf,
    const float* __restrict__ wco, float* __restrict__ out)
{
    extern __shared__ char smem[];
    const uint32_t sb = smem_u32(smem);
    const int tid = threadIdx.x;
    const int wid = tid >> 5, lane = tid & 31;
    const int wm = wid & 1, wn = wid >> 1;   // 2 x 4 warp grid, warp tile 64x64
    const int mt = blockIdx.x, nt = blockIdx.y;
    const int m0 = mt * 128, n0 = nt * 256;

    float acc[4][8][4];
#pragma unroll
    for (int i = 0; i < 4; i++)
#pragma unroll
        for (int j = 0; j < 8; j++)
#pragma unroll
            for (int v = 0; v < 4; v++) acc[i][j][v] = 0.f;

    // stage loader: 3072 x 16B (A 1024 + B 2048), swizzled 128B rows
    auto issue_stage = [&](int kc, int buf) {
        const uint32_t st = sb + buf * STG;
        const size_t kof = (size_t)kc * BK;
#pragma unroll
        for (int i = tid; i < 3072; i += GT) {
            uint32_t dst; const __half* src;
            if (i < 1024) {
                int r = i >> 3, c = i & 7;
                src = g_A + (size_t)(m0 + r) * KTOT + kof + c * 8;
                dst = st + r * 128 + ((c ^ (r & 7)) << 4);
            } else {
                int j = i - 1024, r = j >> 3, c = j & 7;
                src = g_B + (size_t)(n0 + r) * KTOT + kof + c * 8;
                dst = st + 16384 + r * 128 + ((c ^ (r & 7)) << 4);
            }
            cp16(dst, src);
        }
        cp_commit();
    };

    issue_stage(0, 0);
    issue_stage(1, 1);
    issue_stage(2, 2);

    for (int kc = 0; kc < NITER; kc++) {
        if      (kc + 2 < NITER) cp_wait<2>();
        else if (kc + 1 < NITER) cp_wait<1>();
        else                     cp_wait<0>();
        __syncthreads();

        const uint32_t st = sb + (kc & 3) * STG;
#pragma unroll
        for (int kk = 0; kk < 4; kk++) {          // four k16 steps
            uint32_t a_f[4][4];
#pragma unroll
            for (int mi = 0; mi < 4; mi++) {
                int r = wm * 64 + mi * 16 + (lane & 15);
                int c = kk * 2 + (lane >> 4);
                ldsm4(a_f[mi], st + r * 128 + ((c ^ (r & 7)) << 4));
            }
            uint32_t b_f[4][4];
#pragma unroll
            for (int nj = 0; nj < 4; nj++) {
                int r = wn * 64 + nj * 16 + (lane & 7) + ((lane >> 4) << 3);
                int c = kk * 2 + ((lane >> 3) & 1);
                ldsm4(b_f[nj], st + 16384 + r * 128 + ((c ^ (r & 7)) << 4));
            }
#pragma unroll
            for (int mi = 0; mi < 4; mi++)
#pragma unroll
                for (int nj = 0; nj < 4; nj++) {
                    mma_f16(acc[mi][nj * 2],     a_f[mi], &b_f[nj][0]);
                    mma_f16(acc[mi][nj * 2 + 1], a_f[mi], &b_f[nj][2]);
                }
        }
        __syncthreads();
        if (kc + 3 < NITER) issue_stage(kc + 3, (kc + 3) & 3);
    }

    // ---- epilogue: acc -> smem pre[128][260], fused peephole LSTM ----
    float* pre = (float*)smem;
    const int lr = lane >> 2, lc = (lane & 3) * 2;
#pragma unroll
    for (int mi = 0; mi < 4; mi++)
#pragma unroll
        for (int ni = 0; ni < 8; ni++) {
            int r = wm * 64 + mi * 16 + lr;
            int c = wn * 64 + ni * 8 + lc;
            pre[r * 260 + c]           = acc[mi][ni][0];
            pre[r * 260 + c + 1]       = acc[mi][ni][1];
            pre[(r + 8) * 260 + c]     = acc[mi][ni][2];
            pre[(r + 8) * 260 + c + 1] = acc[mi][ni][3];
        }
    __syncthreads();

    const size_t base2 = (size_t)NB * DH * 64;
    for (int e = tid; e < 4 * 2048; e += GT) {
        int img = e >> 11, cl = (e >> 6) & 31, pix = e & 63;
        int col = img * 64 + pix;
        int n = nt * 4 + img;
        int c = mt * 32 + cl;
        const float* c0p = hs + ((size_t)(n * 2) + 1) * DH * 64;

        float pi = pre[(cl)      * 260 + col] + bi[c];
        float pf = pre[(32 + cl) * 260 + col] + bf_[c];
        float pg = pre[(64 + cl) * 260 + col] + bg[c];
        float po = pre[(96 + cl) * 260 + col] + bo[c];
        float c0 = c0p[(size_t)c * 64 + pix];
        float ig = 1.f / (1.f + expf(-(pi + c0 * wci[c * 64 + pix])));
        float fg = 1.f / (1.f + expf(-(pf + c0 * wcf[c * 64 + pix])));
        float gg = tanhf(pg);
        float ct = fg * c0 + ig * gg;
        float og = 1.f / (1.f + expf(-(po + ct * wco[c * 64 + pix])));
        float ht = og * tanhf(ct);
        out[((size_t)n * DH + c) * 64 + pix] = og;
        out[base2 + (((size_t)n * 2) * DH + c) * 64 + pix] = ht;
        out[base2 + (((size_t)n * 2 + 1) * DH + c) * 64 + pix] = ct;
    }
}

extern "C" void kernel_launch(void* const* d_in, const int* in_sizes, int n_in,
                              void* d_out, int out_size) {
    (void)in_sizes; (void)n_in; (void)out_size;
    const float* x  = (const float*)d_in[0];
    const float* hs = (const float*)d_in[1];

    static int configured = 0;
    if (!configured) {
        cudaFuncSetAttribute(gemm_lstm, cudaFuncAttributeMaxDynamicSharedMemorySize,
                             SMEM_BYTES);
        configured = 1;
    }

    prep_a<<<(int)(((size_t)MTOT * KTOT + 255) / 256), 256>>>(
        (const float*)d_in[2], (const float*)d_in[3], (const float*)d_in[4],
        (const float*)d_in[5], (const float*)d_in[6], (const float*)d_in[7],
        (const float*)d_in[8], (const float*)d_in[9]);
    prep_b<<<NTOT, 256>>>(x, hs);

    dim3 grid(MTOT / 128, NTOT / 256);   // 16 x 64
    gemm_lstm<<<grid, GT, SMEM_BYTES>>>(
        hs,
        (const float*)d_in[10], (const float*)d_in[11],
        (const float*)d_in[12], (const float*)d_in[13],
        (const float*)d_in[14], (const float*)d_in[15], (const float*)d_in[16],
        (float*)d_out);
}

// round 8
// speedup vs baseline: 12.7989x; 1.2491x over previous
#include <cuda_runtime.h>
#include <cuda_fp16.h>
#include <cstdint>

#define DIN   256
#define DH    512
#define NB    256
#define KW    768            // Winograd GEMM K = cin total
#define MTOT  2048
#define NT2   4096           // 256 imgs * 16 tiles
#define BK    64
#define NITER (KW/BK)        // 12
#define GT    256
#define STG   49152          // A 16KB + B 32KB per stage
#define SMEM_BYTES (4*STG)   // 192KB
#define SMSTRIDE 2052        // float4-aligned padded stride for sM

__device__ __align__(16) __half g_Aw[(size_t)16*MTOT*KW];   // [p][m][k]
__device__ __align__(16) __half g_Bw[(size_t)16*NT2*KW];    // [p][ncol][k]
__device__ __align__(16) float  g_M [(size_t)16*MTOT*NT2];  // [p][m][ncol]

__device__ __forceinline__ uint32_t smem_u32(const void* p) {
    uint32_t a;
    asm("{ .reg .u64 t; cvta.to.shared.u64 t, %1; cvt.u32.u64 %0, t; }" : "=r"(a) : "l"(p));
    return a;
}
__device__ __forceinline__ void cp16(uint32_t dst, const void* src) {
    asm volatile("cp.async.cg.shared.global [%0], [%1], 16;" :: "r"(dst), "l"(src));
}
__device__ __forceinline__ void cp_commit() { asm volatile("cp.async.commit_group;"); }
template<int N> __device__ __forceinline__ void cp_wait() {
    asm volatile("cp.async.wait_group %0;" :: "n"(N));
}
__device__ __forceinline__ void ldsm4(uint32_t* r, uint32_t a) {
    asm volatile("ldmatrix.sync.aligned.m8n8.x4.shared.b16 {%0,%1,%2,%3}, [%4];"
                 : "=r"(r[0]), "=r"(r[1]), "=r"(r[2]), "=r"(r[3]) : "r"(a));
}
__device__ __forceinline__ void mma_f16(float* d, const uint32_t* a, const uint32_t* b) {
    asm volatile(
        "mma.sync.aligned.m16n8k16.row.col.f32.f16.f16.f32 "
        "{%0,%1,%2,%3}, {%4,%5,%6,%7}, {%8,%9}, {%0,%1,%2,%3};"
        : "+f"(d[0]), "+f"(d[1]), "+f"(d[2]), "+f"(d[3])
        : "r"(a[0]), "r"(a[1]), "r"(a[2]), "r"(a[3]), "r"(b[0]), "r"(b[1]));
}

// ---- prep A: weights -> U = G g G^T per point, row-permuted (cb,gate,cl) ----
__global__ void prep_aw(const float* __restrict__ wii, const float* __restrict__ wif_,
                        const float* __restrict__ wig, const float* __restrict__ wio,
                        const float* __restrict__ whi, const float* __restrict__ whf,
                        const float* __restrict__ whg, const float* __restrict__ who) {
    size_t idx = (size_t)blockIdx.x * blockDim.x + threadIdx.x;
    if (idx >= (size_t)MTOT * KW) return;
    int m = (int)(idx / KW);
    int cin = (int)(idx - (size_t)m * KW);
    int cb = m >> 7, g = (m >> 5) & 3, cl = m & 31;
    int c = cb * 32 + cl;
    const float* wx = (g == 0) ? wii : (g == 1) ? wif_ : (g == 2) ? wig : wio;
    const float* wh = (g == 0) ? whi : (g == 1) ? whf : (g == 2) ? whg : who;
    const float* w9 = (cin < DIN) ? (wx + ((size_t)c * DIN + cin) * 9)
                                  : (wh + ((size_t)c * DH + (cin - DIN)) * 9);
    float gw[3][3];
#pragma unroll
    for (int i = 0; i < 9; i++) gw[i / 3][i % 3] = w9[i];
    float W[4][3];
#pragma unroll
    for (int l = 0; l < 3; l++) {
        W[0][l] = gw[0][l];
        W[1][l] = 0.5f * (gw[0][l] + gw[1][l] + gw[2][l]);
        W[2][l] = 0.5f * (gw[0][l] - gw[1][l] + gw[2][l]);
        W[3][l] = gw[2][l];
    }
#pragma unroll
    for (int i = 0; i < 4; i++) {
        float U0 = W[i][0];
        float U1 = 0.5f * (W[i][0] + W[i][1] + W[i][2]);
        float U2 = 0.5f * (W[i][0] - W[i][1] + W[i][2]);
        float U3 = W[i][2];
        g_Aw[((size_t)(i * 4 + 0) * MTOT + m) * KW + cin] = __float2half(U0);
        g_Aw[((size_t)(i * 4 + 1) * MTOT + m) * KW + cin] = __float2half(U1);
        g_Aw[((size_t)(i * 4 + 2) * MTOT + m) * KW + cin] = __float2half(U2);
        g_Aw[((size_t)(i * 4 + 3) * MTOT + m) * KW + cin] = __float2half(U3);
    }
}

// ---- prep B: reflect-pad gather + V = B^T d B per 4x4 tile ----
__global__ void prep_bw(const float* __restrict__ x, const float* __restrict__ hs) {
    __shared__ float sd[96][100];
    const int img = blockIdx.x;
    const int tid = threadIdx.x;
    for (int ch = 0; ch < 8; ch++) {
        __syncthreads();
        for (int i = tid; i < 96 * 100; i += GT) {
            int ci = i / 100, pp = i - ci * 100;
            int yy = pp / 10, xx = pp - yy * 10;
            int ry = (yy == 0) ? 1 : ((yy == 9) ? 6 : yy - 1);
            int rx = (xx == 0) ? 1 : ((xx == 9) ? 6 : xx - 1);
            int cg = ch * 96 + ci;
            const float* src = (cg < DIN)
                ? x  + ((size_t)img * DIN + cg) * 64
                : hs + (((size_t)img * 2) * DH + (cg - DIN)) * 64;
            sd[ci][pp] = src[ry * 8 + rx];
        }
        __syncthreads();
        for (int e = tid; e < 96 * 16; e += GT) {
            int ci = e % 96, t = e / 96;
            int ty = t >> 2, tx = t & 3;
            int cg = ch * 96 + ci;
            float d[4][4];
#pragma unroll
            for (int k = 0; k < 4; k++)
#pragma unroll
                for (int l = 0; l < 4; l++)
                    d[k][l] = sd[ci][(2 * ty + k) * 10 + 2 * tx + l];
            float W[4][4];
#pragma unroll
            for (int l = 0; l < 4; l++) {
                W[0][l] = d[0][l] - d[2][l];
                W[1][l] = d[1][l] + d[2][l];
                W[2][l] = d[2][l] - d[1][l];
                W[3][l] = d[1][l] - d[3][l];
            }
            size_t col = (size_t)img * 16 + t;
#pragma unroll
            for (int i = 0; i < 4; i++) {
                float V0 = W[i][0] - W[i][2];
                float V1 = W[i][1] + W[i][2];
                float V2 = W[i][2] - W[i][1];
                float V3 = W[i][1] - W[i][3];
                g_Bw[((size_t)(i * 4 + 0) * NT2 + col) * KW + cg] = __float2half(V0);
                g_Bw[((size_t)(i * 4 + 1) * NT2 + col) * KW + cg] = __float2half(V1);
                g_Bw[((size_t)(i * 4 + 2) * NT2 + col) * KW + cg] = __float2half(V2);
                g_Bw[((size_t)(i * 4 + 3) * NT2 + col) * KW + cg] = __float2half(V3);
            }
        }
    }
}

// ---- point GEMM: M_p[2048][4096] = U_p (2048x768) * V_p^T ----
__global__ void __launch_bounds__(GT, 1) gemm_wino(int dummy) {
    extern __shared__ char smem[];
    const uint32_t sb = smem_u32(smem);
    const int tid = threadIdx.x;
    const int wid = tid >> 5, lane = tid & 31;
    const int wm = wid & 1, wn = wid >> 1;
    const int mt = blockIdx.x, nt = blockIdx.y, p = blockIdx.z;
    const int m0 = mt * 128, n0 = nt * 256;
    const __half* Ap = g_Aw + (size_t)p * MTOT * KW;
    const __half* Bp = g_Bw + (size_t)p * NT2 * KW;

    float acc[4][8][4];
#pragma unroll
    for (int i = 0; i < 4; i++)
#pragma unroll
        for (int j = 0; j < 8; j++)
#pragma unroll
            for (int v = 0; v < 4; v++) acc[i][j][v] = 0.f;

    auto issue_stage = [&](int kc, int buf) {
        const uint32_t st = sb + buf * STG;
        const size_t kof = (size_t)kc * BK;
#pragma unroll
        for (int i = tid; i < 3072; i += GT) {
            uint32_t dst; const __half* src;
            if (i < 1024) {
                int r = i >> 3, c = i & 7;
                src = Ap + (size_t)(m0 + r) * KW + kof + c * 8;
                dst = st + r * 128 + ((c ^ (r & 7)) << 4);
            } else {
                int j = i - 1024, r = j >> 3, c = j & 7;
                src = Bp + (size_t)(n0 + r) * KW + kof + c * 8;
                dst = st + 16384 + r * 128 + ((c ^ (r & 7)) << 4);
            }
            cp16(dst, src);
        }
        cp_commit();
    };

    issue_stage(0, 0);
    issue_stage(1, 1);
    issue_stage(2, 2);

    for (int kc = 0; kc < NITER; kc++) {
        if      (kc + 2 < NITER) cp_wait<2>();
        else if (kc + 1 < NITER) cp_wait<1>();
        else                     cp_wait<0>();
        __syncthreads();

        const uint32_t st = sb + (kc & 3) * STG;
#pragma unroll
        for (int kk = 0; kk < 4; kk++) {
            uint32_t a_f[4][4];
#pragma unroll
            for (int mi = 0; mi < 4; mi++) {
                int r = wm * 64 + mi * 16 + (lane & 15);
                int c = kk * 2 + (lane >> 4);
                ldsm4(a_f[mi], st + r * 128 + ((c ^ (r & 7)) << 4));
            }
            uint32_t b_f[4][4];
#pragma unroll
            for (int nj = 0; nj < 4; nj++) {
                int r = wn * 64 + nj * 16 + (lane & 7) + ((lane >> 4) << 3);
                int c = kk * 2 + ((lane >> 3) & 1);
                ldsm4(b_f[nj], st + 16384 + r * 128 + ((c ^ (r & 7)) << 4));
            }
#pragma unroll
            for (int mi = 0; mi < 4; mi++)
#pragma unroll
                for (int nj = 0; nj < 4; nj++) {
                    mma_f16(acc[mi][nj * 2],     a_f[mi], &b_f[nj][0]);
                    mma_f16(acc[mi][nj * 2 + 1], a_f[mi], &b_f[nj][2]);
                }
        }
        __syncthreads();
        if (kc + 3 < NITER) issue_stage(kc + 3, (kc + 3) & 3);
    }

    float* pre = (float*)smem;
    const int lr = lane >> 2, lc = (lane & 3) * 2;
#pragma unroll
    for (int mi = 0; mi < 4; mi++)
#pragma unroll
        for (int ni = 0; ni < 8; ni++) {
            int r = wm * 64 + mi * 16 + lr;
            int c = wn * 64 + ni * 8 + lc;
            pre[r * 260 + c]           = acc[mi][ni][0];
            pre[r * 260 + c + 1]       = acc[mi][ni][1];
            pre[(r + 8) * 260 + c]     = acc[mi][ni][2];
            pre[(r + 8) * 260 + c + 1] = acc[mi][ni][3];
        }
    __syncthreads();
    float* Mp = g_M + (size_t)p * MTOT * NT2;
    for (int e = tid; e < 128 * 256 / 4; e += GT) {
        int r = e / 64, c4 = (e % 64) * 4;
        float4 v = *(float4*)&pre[r * 260 + c4];
        *(float4*)&Mp[(size_t)(m0 + r) * NT2 + n0 + c4] = v;
    }
    (void)dummy;
}

// ---- inverse transform + fused peephole LSTM ----
#define SM_LSTM ((16 * SMSTRIDE + 128 * 66) * 4)
__global__ void __launch_bounds__(GT, 1) lstm_wino(
    const float* __restrict__ hs,
    const float* __restrict__ bi, const float* __restrict__ bf_,
    const float* __restrict__ bg, const float* __restrict__ bo,
    const float* __restrict__ wci, const float* __restrict__ wcf,
    const float* __restrict__ wco, float* __restrict__ out)
{
    extern __shared__ float sm[];
    float* sM   = sm;                       // [p*SMSTRIDE + r*16 + t]
    float* pre2 = sm + 16 * SMSTRIDE;       // [128][66]
    const int tid = threadIdx.x;
    const int cb = blockIdx.x, img = blockIdx.y;

    for (int s = tid; s < 16 * 128; s += GT) {
        int p = s >> 7, r = s & 127;
        const float4* src = (const float4*)(g_M
            + ((size_t)p * MTOT + cb * 128 + r) * NT2 + (size_t)img * 16);
        float4 v0 = src[0], v1 = src[1], v2 = src[2], v3 = src[3];
        float* d = &sM[p * SMSTRIDE + r * 16];
        *(float4*)(d)      = v0; *(float4*)(d + 4)  = v1;
        *(float4*)(d + 8)  = v2; *(float4*)(d + 12) = v3;
    }
    __syncthreads();

    for (int e = tid; e < 128 * 16; e += GT) {
        int r = e & 127, t = e >> 7;
        int ty = t >> 2, tx = t & 3;
        float M[4][4];
#pragma unroll
        for (int i = 0; i < 4; i++)
#pragma unroll
            for (int j = 0; j < 4; j++)
                M[i][j] = sM[(i * 4 + j) * SMSTRIDE + r * 16 + t];
        float t0[4], t1[4];
#pragma unroll
        for (int j = 0; j < 4; j++) {
            t0[j] = M[0][j] + M[1][j] + M[2][j];
            t1[j] = M[1][j] - M[2][j] - M[3][j];
        }
        float y00 = t0[0] + t0[1] + t0[2];
        float y01 = t0[1] - t0[2] - t0[3];
        float y10 = t1[0] + t1[1] + t1[2];
        float y11 = t1[1] - t1[2] - t1[3];
        float* dst = &pre2[r * 66 + (2 * ty) * 8 + 2 * tx];
        dst[0] = y00; dst[1] = y01; dst[8] = y10; dst[9] = y11;
    }
    __syncthreads();

    const int n = img;
    const float* c0p = hs + ((size_t)(n * 2) + 1) * DH * 64;
    const size_t base2 = (size_t)NB * DH * 64;
    for (int e = tid; e < 32 * 64; e += GT) {
        int cl = e >> 6, pix = e & 63;
        int c = cb * 32 + cl;
        float pi = pre2[(cl)      * 66 + pix] + bi[c];
        float pf = pre2[(32 + cl) * 66 + pix] + bf_[c];
        float pg = pre2[(64 + cl) * 66 + pix] + bg[c];
        float po = pre2[(96 + cl) * 66 + pix] + bo[c];
        float c0 = c0p[(size_t)c * 64 + pix];
        float ig = 1.f / (1.f + expf(-(pi + c0 * wci[c * 64 + pix])));
        float fg = 1.f / (1.f + expf(-(pf + c0 * wcf[c * 64 + pix])));
        float gg = tanhf(pg);
        float ct = fg * c0 + ig * gg;
        float og = 1.f / (1.f + expf(-(po + ct * wco[c * 64 + pix])));
        float ht = og * tanhf(ct);
        out[((size_t)n * DH + c) * 64 + pix] = og;
        out[base2 + (((size_t)n * 2) * DH + c) * 64 + pix] = ht;
        out[base2 + (((size_t)n * 2 + 1) * DH + c) * 64 + pix] = ct;
    }
}

extern "C" void kernel_launch(void* const* d_in, const int* in_sizes, int n_in,
                              void* d_out, int out_size) {
    (void)in_sizes; (void)n_in; (void)out_size;
    const float* x  = (const float*)d_in[0];
    const float* hs = (const float*)d_in[1];

    static int configured = 0;
    if (!configured) {
        cudaFuncSetAttribute(gemm_wino, cudaFuncAttributeMaxDynamicSharedMemorySize,
                             SMEM_BYTES);
        cudaFuncSetAttribute(lstm_wino, cudaFuncAttributeMaxDynamicSharedMemorySize,
                             SM_LSTM);
        configured = 1;
    }

    prep_aw<<<(int)(((size_t)MTOT * KW + 255) / 256), 256>>>(
        (const float*)d_in[2], (const float*)d_in[3], (const float*)d_in[4],
        (const float*)d_in[5], (const float*)d_in[6], (const float*)d_in[7],
        (const float*)d_in[8], (const float*)d_in[9]);
    prep_bw<<<NB, GT>>>(x, hs);

    dim3 ggrid(MTOT / 128, NT2 / 256, 16);
    gemm_wino<<<ggrid, GT, SMEM_BYTES>>>(0);

    dim3 lgrid(MTOT / 128, NB);
    lstm_wino<<<lgrid, GT, SM_LSTM>>>(
        hs,
        (const float*)d_in[10], (const float*)d_in[11],
        (const float*)d_in[12], (const float*)d_in[13],
        (const float*)d_in[14], (const float*)d_in[15], (const float*)d_in[16],
        (float*)d_out);
}

// round 9
// speedup vs baseline: 15.6519x; 1.2229x over previous
#include <cuda_runtime.h>
#include <cuda_fp16.h>
#include <cstdint>

#define DIN   256
#define DH    512
#define NB    256
#define KW    768            // K per Winograd point
#define MTOT  2048
#define NT2   4096           // 256 imgs * 16 tiles
#define BK    64
#define NKC   12             // K chunks per point
#define NCH   (16*NKC)       // 192 global chunks
#define GT    256
#define STG   24576          // A 16KB + B 8KB per stage
#define SMEM_GEMM (4*STG)    // 98304
#define SMEM_EPI  (4*128*66*4) // 135168
#define SMEM_BYTES SMEM_EPI

__device__ __align__(16) __half g_Aw[(size_t)16*MTOT*KW];   // [p][m][k]
__device__ __align__(16) __half g_Bw[(size_t)16*NT2*KW];    // [p][col][k]

__device__ __forceinline__ uint32_t smem_u32(const void* p) {
    uint32_t a;
    asm("{ .reg .u64 t; cvta.to.shared.u64 t, %1; cvt.u32.u64 %0, t; }" : "=r"(a) : "l"(p));
    return a;
}
__device__ __forceinline__ void cp16(uint32_t dst, const void* src) {
    asm volatile("cp.async.cg.shared.global [%0], [%1], 16;" :: "r"(dst), "l"(src));
}
__device__ __forceinline__ void cp_commit() { asm volatile("cp.async.commit_group;"); }
template<int N> __device__ __forceinline__ void cp_wait() {
    asm volatile("cp.async.wait_group %0;" :: "n"(N));
}
__device__ __forceinline__ void ldsm4(uint32_t* r, uint32_t a) {
    asm volatile("ldmatrix.sync.aligned.m8n8.x4.shared.b16 {%0,%1,%2,%3}, [%4];"
                 : "=r"(r[0]), "=r"(r[1]), "=r"(r[2]), "=r"(r[3]) : "r"(a));
}
__device__ __forceinline__ void mma_f16(float* d, const uint32_t* a, const uint32_t* b) {
    asm volatile(
        "mma.sync.aligned.m16n8k16.row.col.f32.f16.f16.f32 "
        "{%0,%1,%2,%3}, {%4,%5,%6,%7}, {%8,%9}, {%0,%1,%2,%3};"
        : "+f"(d[0]), "+f"(d[1]), "+f"(d[2]), "+f"(d[3])
        : "r"(a[0]), "r"(a[1]), "r"(a[2]), "r"(a[3]), "r"(b[0]), "r"(b[1]));
}

// ---- prep A: weights -> U = G g G^T, rows (cb,gate,cl) ----
__global__ void prep_aw(const float* __restrict__ wii, const float* __restrict__ wif_,
                        const float* __restrict__ wig, const float* __restrict__ wio,
                        const float* __restrict__ whi, const float* __restrict__ whf,
                        const float* __restrict__ whg, const float* __restrict__ who) {
    size_t idx = (size_t)blockIdx.x * blockDim.x + threadIdx.x;
    if (idx >= (size_t)MTOT * KW) return;
    int m = (int)(idx / KW);
    int cin = (int)(idx - (size_t)m * KW);
    int cb = m >> 7, g = (m >> 5) & 3, cl = m & 31;
    int c = cb * 32 + cl;
    const float* wx = (g == 0) ? wii : (g == 1) ? wif_ : (g == 2) ? wig : wio;
    const float* wh = (g == 0) ? whi : (g == 1) ? whf : (g == 2) ? whg : who;
    const float* w9 = (cin < DIN) ? (wx + ((size_t)c * DIN + cin) * 9)
                                  : (wh + ((size_t)c * DH + (cin - DIN)) * 9);
    float gw[3][3];
#pragma unroll
    for (int i = 0; i < 9; i++) gw[i / 3][i % 3] = w9[i];
    float W[4][3];
#pragma unroll
    for (int l = 0; l < 3; l++) {
        W[0][l] = gw[0][l];
        W[1][l] = 0.5f * (gw[0][l] + gw[1][l] + gw[2][l]);
        W[2][l] = 0.5f * (gw[0][l] - gw[1][l] + gw[2][l]);
        W[3][l] = gw[2][l];
    }
#pragma unroll
    for (int i = 0; i < 4; i++) {
        float U[4];
        U[0] = W[i][0];
        U[1] = 0.5f * (W[i][0] + W[i][1] + W[i][2]);
        U[2] = 0.5f * (W[i][0] - W[i][1] + W[i][2]);
        U[3] = W[i][2];
#pragma unroll
        for (int j = 0; j < 4; j++)
            g_Aw[((size_t)(i * 4 + j) * MTOT + m) * KW + cin] = __float2half(U[j]);
    }
}

// ---- prep B: reflect-pad gather + V = B^T d B ----
__global__ void prep_bw(const float* __restrict__ x, const float* __restrict__ hs) {
    __shared__ float sd[96][100];
    const int img = blockIdx.x;
    const int tid = threadIdx.x;
    for (int ch = 0; ch < 8; ch++) {
        __syncthreads();
        for (int i = tid; i < 96 * 100; i += GT) {
            int ci = i / 100, pp = i - ci * 100;
            int yy = pp / 10, xx = pp - yy * 10;
            int ry = (yy == 0) ? 1 : ((yy == 9) ? 6 : yy - 1);
            int rx = (xx == 0) ? 1 : ((xx == 9) ? 6 : xx - 1);
            int cg = ch * 96 + ci;
            const float* src = (cg < DIN)
                ? x  + ((size_t)img * DIN + cg) * 64
                : hs + (((size_t)img * 2) * DH + (cg - DIN)) * 64;
            sd[ci][pp] = src[ry * 8 + rx];
        }
        __syncthreads();
        for (int e = tid; e < 96 * 16; e += GT) {
            int ci = e % 96, t = e / 96;
            int ty = t >> 2, tx = t & 3;
            int cg = ch * 96 + ci;
            float d[4][4];
#pragma unroll
            for (int k = 0; k < 4; k++)
#pragma unroll
                for (int l = 0; l < 4; l++)
                    d[k][l] = sd[ci][(2 * ty + k) * 10 + 2 * tx + l];
            float W[4][4];
#pragma unroll
            for (int l = 0; l < 4; l++) {
                W[0][l] = d[0][l] - d[2][l];
                W[1][l] = d[1][l] + d[2][l];
                W[2][l] = d[2][l] - d[1][l];
                W[3][l] = d[1][l] - d[3][l];
            }
            size_t col = (size_t)img * 16 + t;
#pragma unroll
            for (int i = 0; i < 4; i++) {
                float V[4];
                V[0] = W[i][0] - W[i][2];
                V[1] = W[i][1] + W[i][2];
                V[2] = W[i][2] - W[i][1];
                V[3] = W[i][1] - W[i][3];
#pragma unroll
                for (int j = 0; j < 4; j++)
                    g_Bw[((size_t)(i * 4 + j) * NT2 + col) * KW + cg] = __float2half(V[j]);
            }
        }
    }
}

// ---- fused: 16 point-GEMMs + on-the-fly inverse transform + LSTM ----
__global__ void __launch_bounds__(GT, 1) gemm_fused(
    const float* __restrict__ hs,
    const float* __restrict__ bi, const float* __restrict__ bf_,
    const float* __restrict__ bg, const float* __restrict__ bo,
    const float* __restrict__ wci, const float* __restrict__ wcf,
    const float* __restrict__ wco, float* __restrict__ out)
{
    extern __shared__ char smem[];
    const uint32_t sb = smem_u32(smem);
    const int tid = threadIdx.x;
    const int wid = tid >> 5, lane = tid & 31;
    const int wm = wid & 1, wn = wid >> 1;    // 2x4 warps, warp tile 64x16
    const int mt = blockIdx.x, nt = blockIdx.y;
    const int m0 = mt * 128, n0 = nt * 64;

    float outr[4][2][4][4];                   // [mi][s][v][a*2+b]
#pragma unroll
    for (int i = 0; i < 4; i++)
#pragma unroll
        for (int s = 0; s < 2; s++)
#pragma unroll
            for (int v = 0; v < 4; v++)
#pragma unroll
                for (int q = 0; q < 4; q++) outr[i][s][v][q] = 0.f;

    auto issue_stage = [&](int cc, int buf) {
        const uint32_t st = sb + buf * STG;
        int p = cc / NKC, kc = cc - p * NKC;
        const __half* Ap = g_Aw + (size_t)p * MTOT * KW;
        const __half* Bp = g_Bw + (size_t)p * NT2 * KW;
        const size_t kof = (size_t)kc * BK;
#pragma unroll
        for (int i = tid; i < 1536; i += GT) {
            uint32_t dst; const __half* src;
            if (i < 1024) {
                int r = i >> 3, c = i & 7;
                src = Ap + (size_t)(m0 + r) * KW + kof + c * 8;
                dst = st + r * 128 + ((c ^ (r & 7)) << 4);
            } else {
                int j = i - 1024, r = j >> 3, c = j & 7;
                src = Bp + (size_t)(n0 + r) * KW + kof + c * 8;
                dst = st + 16384 + r * 128 + ((c ^ (r & 7)) << 4);
            }
            cp16(dst, src);
        }
        cp_commit();
    };

    issue_stage(0, 0);
    issue_stage(1, 1);
    issue_stage(2, 2);

    for (int p = 0; p < 16; p++) {
        float acc[4][2][4];
#pragma unroll
        for (int i = 0; i < 4; i++)
#pragma unroll
            for (int s = 0; s < 2; s++)
#pragma unroll
                for (int v = 0; v < 4; v++) acc[i][s][v] = 0.f;

        for (int kc = 0; kc < NKC; kc++) {
            int cc = p * NKC + kc;
            if      (cc + 2 < NCH) cp_wait<2>();
            else if (cc + 1 < NCH) cp_wait<1>();
            else                   cp_wait<0>();
            __syncthreads();

            const uint32_t st = sb + (cc & 3) * STG;
#pragma unroll
            for (int kk = 0; kk < 4; kk++) {
                uint32_t a_f[4][4];
#pragma unroll
                for (int mi = 0; mi < 4; mi++) {
                    int r = wm * 64 + mi * 16 + (lane & 15);
                    int c = kk * 2 + (lane >> 4);
                    ldsm4(a_f[mi], st + r * 128 + ((c ^ (r & 7)) << 4));
                }
                uint32_t b_f[4];
                {
                    int r = wn * 16 + (lane & 7) + ((lane >> 4) << 3);
                    int c = kk * 2 + ((lane >> 3) & 1);
                    ldsm4(b_f, st + 16384 + r * 128 + ((c ^ (r & 7)) << 4));
                }
#pragma unroll
                for (int mi = 0; mi < 4; mi++) {
                    mma_f16(acc[mi][0], a_f[mi], &b_f[0]);
                    mma_f16(acc[mi][1], a_f[mi], &b_f[2]);
                }
            }
            __syncthreads();
            if (cc + 3 < NCH) issue_stage(cc + 3, (cc + 3) & 3);
        }

        // inverse-transform coefficients for this point p = (i,j)
        int pi_ = p >> 2, pj = p & 3;
        float ca0 = (pi_ == 3) ? 0.f : 1.f;                       // At[0] = 1,1,1,0
        float ca1 = (pi_ == 0) ? 0.f : ((pi_ == 1) ? 1.f : -1.f); // At[1] = 0,1,-1,-1
        float cb0 = (pj  == 3) ? 0.f : 1.f;
        float cb1 = (pj  == 0) ? 0.f : ((pj  == 1) ? 1.f : -1.f);
        float c00 = ca0 * cb0, c01 = ca0 * cb1, c10 = ca1 * cb0, c11 = ca1 * cb1;
#pragma unroll
        for (int mi = 0; mi < 4; mi++)
#pragma unroll
            for (int s = 0; s < 2; s++)
#pragma unroll
                for (int v = 0; v < 4; v++) {
                    float m = acc[mi][s][v];
                    outr[mi][s][v][0] += c00 * m;
                    outr[mi][s][v][1] += c01 * m;
                    outr[mi][s][v][2] += c10 * m;
                    outr[mi][s][v][3] += c11 * m;
                }
    }

    // ---- epilogue: outr -> pre2[4 imgs][128 rows][66], then LSTM ----
    __syncthreads();
    float* pre2 = (float*)smem;
    const int lr = lane >> 2, lc = (lane & 3) * 2;
#pragma unroll
    for (int mi = 0; mi < 4; mi++)
#pragma unroll
        for (int s = 0; s < 2; s++)
#pragma unroll
            for (int v = 0; v < 4; v++) {
                int row = wm * 64 + mi * 16 + lr + ((v >> 1) << 3);
                int col = wn * 16 + s * 8 + lc + (v & 1);
                int img = col >> 4, t = col & 15;
                int ty = t >> 2, tx = t & 3;
                float* dst = &pre2[((img * 128) + row) * 66 + (2 * ty) * 8 + 2 * tx];
                dst[0] = outr[mi][s][v][0];
                dst[1] = outr[mi][s][v][1];
                dst[8] = outr[mi][s][v][2];
                dst[9] = outr[mi][s][v][3];
            }
    __syncthreads();

    const size_t base2 = (size_t)NB * DH * 64;
    for (int e = tid; e < 4 * 32 * 64; e += GT) {
        int img = e >> 11, cl = (e >> 6) & 31, pix = e & 63;
        int n = nt * 4 + img;
        int c = mt * 32 + cl;
        const float* pr = &pre2[(size_t)img * 128 * 66];
        const float* c0p = hs + ((size_t)(n * 2) + 1) * DH * 64;
        float pi = pr[(cl)      * 66 + pix] + bi[c];
        float pf = pr[(32 + cl) * 66 + pix] + bf_[c];
        float pg = pr[(64 + cl) * 66 + pix] + bg[c];
        float po = pr[(96 + cl) * 66 + pix] + bo[c];
        float c0 = c0p[(size_t)c * 64 + pix];
        float ig = 1.f / (1.f + expf(-(pi + c0 * wci[c * 64 + pix])));
        float fg = 1.f / (1.f + expf(-(pf + c0 * wcf[c * 64 + pix])));
        float gg = tanhf(pg);
        float ct = fg * c0 + ig * gg;
        float og = 1.f / (1.f + expf(-(po + ct * wco[c * 64 + pix])));
        float ht = og * tanhf(ct);
        out[((size_t)n * DH + c) * 64 + pix] = og;
        out[base2 + (((size_t)n * 2) * DH + c) * 64 + pix] = ht;
        out[base2 + (((size_t)n * 2 + 1) * DH + c) * 64 + pix] = ct;
    }
}

extern "C" void kernel_launch(void* const* d_in, const int* in_sizes, int n_in,
                              void* d_out, int out_size) {
    (void)in_sizes; (void)n_in; (void)out_size;
    const float* x  = (const float*)d_in[0];
    const float* hs = (const float*)d_in[1];

    cudaFuncSetAttribute(gemm_fused, cudaFuncAttributeMaxDynamicSharedMemorySize,
                         SMEM_BYTES);

    prep_aw<<<(int)(((size_t)MTOT * KW + 255) / 256), 256>>>(
        (const float*)d_in[2], (const float*)d_in[3], (const float*)d_in[4],
        (const float*)d_in[5], (const float*)d_in[6], (const float*)d_in[7],
        (const float*)d_in[8], (const float*)d_in[9]);
    prep_bw<<<NB, GT>>>(x, hs);

    dim3 grid(MTOT / 128, NT2 / 64);   // 16 x 64 = 1024 CTAs
    gemm_fused<<<grid, GT, SMEM_BYTES>>>(
        hs,
        (const float*)d_in[10], (const float*)d_in[11],
        (const float*)d_in[12], (const float*)d_in[13],
        (const float*)d_in[14], (const float*)d_in[15], (const float*)d_in[16],
        (float*)d_out);
}